// round 6
// baseline (speedup 1.0000x reference)
#include <cuda_runtime.h>
#include <cuda_fp16.h>
#include <math.h>

#define BATCH 8
#define N 2048
#define BN (BATCH * N)
#define TOTE (BATCH * N * N)          // 33554432 elements
#define NPART 64
#define NITER 50

#define EPSF   0.01f
#define BIGF   1e20f
#define HUGEF  1e30f
#define SMALLF 1e-7f
#define DXY    (1.0f / 2048.0f)

static constexpr float INVE = 1.0f / 0.01f;          // 1/eps
static constexpr float PC   = 1.0f / (1.0f + 0.01f); // p_coef

// ---------------- device state ----------------
// g_buf (128 MB), phase-aliased:
//  Loop phase:   [0,4MB)   row masks (BN rows x 64 u32 words)
//                [4,8MB)   col masks (BN cols x 64 u32 words)
//                [8,32MB)  packed fp16 CSR values (cap 12M entries)
//                [32,56MB) packed fp16 CSC values (cap 12M entries)
//  Final phase:  whole buffer = fallback fp32 K target (sparse data dead)
static __device__ float4 g_buf[TOTE / 4];        // 128 MB
static __device__ float g_u[BN];
static __device__ float g_v[BN];
static __device__ float g_a[BN];
static __device__ float g_aprev[BN];
static __device__ float g_b[BN];
static __device__ float g_part[NPART][BN];       // finals only
static __device__ float g_rowsum[BN];
static __device__ float g_rowkc[BN];
static __device__ unsigned g_rbase[BN];
static __device__ unsigned g_cbase[BN];
static __device__ unsigned g_rcnt;
static __device__ unsigned g_ccnt;
static __device__ unsigned g_maxa[64];
static __device__ unsigned g_maxb[64];

__device__ __forceinline__ unsigned* rmask() { return (unsigned*)g_buf; }
__device__ __forceinline__ unsigned* cmask() { return (unsigned*)((char*)g_buf + (4u << 20)); }
__device__ __forceinline__ __half*   rvals() { return (__half*)((char*)g_buf + (8u << 20)); }
__device__ __forceinline__ __half*   cvals() { return (__half*)((char*)g_buf + (32u << 20)); }

__device__ __forceinline__ float warp_sum(float x) {
#pragma unroll
    for (int o = 16; o; o >>= 1) x += __shfl_xor_sync(0xFFFFFFFFu, x, o);
    return x;
}

// ---------------- init ----------------
__global__ void init_kernel() {
    int g = blockIdx.x * 256 + threadIdx.x;
    if (g < BN) {
        g_u[g] = 0.0f;
        g_v[g] = 0.0f;
        g_b[g] = 1.0f;
    }
    if (g < 64) { g_maxa[g] = 0u; g_maxb[g] = 0u; }
    if (g == 0) { g_rcnt = 0u; g_ccnt = 0u; }
}

// ---------------- build CSR: masks + packed fp16 values, row-major ----------------
__global__ void __launch_bounds__(256) build_csr(const float* __restrict__ C) {
    __shared__ __half rbuf[8][1024];
    __shared__ unsigned sbase[8];
    const int warp = threadIdx.x >> 5, lane = threadIdx.x & 31;
    const int row = blockIdx.x * 8 + warp;        // grid 2048
    const float* __restrict__ cr = C + (size_t)row * N;
    unsigned cnt = 0;
#pragma unroll 4
    for (int g = 0; g < 64; g++) {
        float c = cr[g * 32 + lane];
        __half h = __float2half_rn(__expf(c * -INVE));
        bool nz = (__half_as_ushort(h) != 0);
        unsigned m = __ballot_sync(0xFFFFFFFFu, nz);
        if (lane == 0) rmask()[(size_t)row * 64 + g] = m;
        unsigned pre = __popc(m & ((1u << lane) - 1u));
        if (nz && cnt + pre < 1024) rbuf[warp][cnt + pre] = h;
        cnt += __popc(m);
    }
    if (lane == 0) {
        unsigned base = atomicAdd(&g_rcnt, cnt);
        sbase[warp] = base;
        g_rbase[row] = base;
    }
    __syncwarp();
    unsigned base = sbase[warp];
    for (unsigned t = lane; t < cnt && t < 1024; t += 32) rvals()[base + t] = rbuf[warp][t];
}

// ---------------- build CSC: masks + packed fp16 values, col-major ----------------
__global__ void __launch_bounds__(256) build_csc(const float* __restrict__ C) {
    __shared__ float tile[32][33];
    __shared__ __half cbuf[32][640];               // 40 KB
    __shared__ unsigned sbase[32];
    const int b  = blockIdx.x >> 6;                // grid 512: b(8) x jg(64)
    const int jg = blockIdx.x & 63;
    const int warp = threadIdx.x >> 5, lane = threadIdx.x & 31;
    unsigned cnt[4] = {0u, 0u, 0u, 0u};

    for (int chunk = 0; chunk < 64; chunk++) {
        int i0 = chunk * 32;
#pragma unroll
        for (int s = 0; s < 4; s++) {
            int il = s * 8 + (threadIdx.x >> 5);
            tile[il][threadIdx.x & 31] =
                C[((size_t)(b * N + i0 + il)) * N + jg * 32 + (threadIdx.x & 31)];
        }
        __syncthreads();
#pragma unroll
        for (int q = 0; q < 4; q++) {
            int jc = warp + q * 8;
            float c = tile[lane][jc];
            __half h = __float2half_rn(__expf(c * -INVE));
            bool nz = (__half_as_ushort(h) != 0);
            unsigned m = __ballot_sync(0xFFFFFFFFu, nz);
            if (lane == 0) cmask()[(size_t)(b * N + jg * 32 + jc) * 64 + chunk] = m;
            unsigned pre = __popc(m & ((1u << lane) - 1u));
            if (nz && cnt[q] + pre < 640) cbuf[jc][cnt[q] + pre] = h;
            cnt[q] += __popc(m);
        }
        __syncthreads();
    }
#pragma unroll
    for (int q = 0; q < 4; q++) {
        int jc = warp + q * 8;
        if (lane == 0) {
            unsigned base = atomicAdd(&g_ccnt, cnt[q]);
            sbase[jc] = base;
            g_cbase[b * N + jg * 32 + jc] = base;
        }
        __syncwarp();
        unsigned base = sbase[jc];
        for (unsigned t = lane; t < cnt[q] && t < 640; t += 32) cvals()[base + t] = cbuf[jc][t];
    }
}

// ---------------- row pass (sparse): s = sum_j K~ b_j dy -> a ----------------
__global__ void __launch_bounds__(256) row_kernel(int it) {
    __shared__ float sbv[N];          // b_j * dy
    __shared__ __half vbuf[8][1024];
    __shared__ float swm[8];
    const int b   = blockIdx.x >> 8;
    const int rb  = blockIdx.x & 255;
    const int tid = threadIdx.x;
    const int prev = (it == 0) ? 63 : (it - 1);
    const bool pabs = (__uint_as_float(g_maxa[prev]) > BIGF) ||
                      (__uint_as_float(g_maxb[prev]) > BIGF);
    const int base = b * N;

    for (int j = tid; j < N; j += 256) {
        float bn = g_b[base + j];
        sbv[j] = bn * DXY;
        if (pabs && rb == 0) g_v[base + j] += EPSF * logf(bn);
    }
    __syncthreads();

    const int warp = tid >> 5, lane = tid & 31;
    const int r = rb * 8 + warp;
    const int row = base + r;
    float u = g_u[row];

    uint2 mw = *(const uint2*)&rmask()[(size_t)row * 64 + 2 * lane];
    unsigned c01 = __popc(mw.x) + __popc(mw.y);
    unsigned inc = c01;
#pragma unroll
    for (int d = 1; d < 32; d <<= 1) {
        unsigned n = __shfl_up_sync(0xFFFFFFFFu, inc, d);
        if (lane >= d) inc += n;
    }
    unsigned total = __shfl_sync(0xFFFFFFFFu, inc, 31);
    unsigned excl = inc - c01;
    unsigned vb = (lane == 0) ? g_rbase[row] : 0u;
    vb = __shfl_sync(0xFFFFFFFFu, vb, 0);

    const __half* __restrict__ src = rvals() + vb;
    unsigned tcl = total < 1024u ? total : 1024u;
    for (unsigned t = lane; t < tcl; t += 32) vbuf[warp][t] = src[t];
    __syncwarp();

    float acc = 0.0f;
    if (!pabs) {
        unsigned o = excl;
        int jb = 64 * lane;
        unsigned m = mw.x;
        while (m) {
            int p = __ffs(m) - 1; m &= m - 1u;
            acc = fmaf(__half2float(vbuf[warp][o++]), sbv[jb + p], acc);
        }
        jb += 32; m = mw.y;
        while (m) {
            int p = __ffs(m) - 1; m &= m - 1u;
            acc = fmaf(__half2float(vbuf[warp][o++]), sbv[jb + p], acc);
        }
    } else {
        // absorb: rescale CSR values by aold * b_j, sum with b=1
        float aold = g_a[row];
        if (lane == 0) g_aprev[row] = aold;
        u += EPSF * logf(aold);
        unsigned o = excl;
        int jb = 64 * lane;
#pragma unroll
        for (int w = 0; w < 2; w++) {
            unsigned m = (w == 0) ? mw.x : mw.y;
            int jo = jb + w * 32;
            while (m) {
                int p = __ffs(m) - 1; m &= m - 1u;
                float braw = sbv[jo + p] * (float)N;
                float kn = fminf(__half2float(vbuf[warp][o]) * aold * braw, HUGEF);
                vbuf[warp][o] = __float2half_rn(kn);
                acc += kn;
                o++;
            }
        }
        __syncwarp();
        __half* dst = rvals() + vb;
        for (unsigned t = lane; t < tcl; t += 32) dst[t] = vbuf[warp][t];
        acc *= DXY;
    }

    acc = warp_sum(acc);
    if (lane == 0) {
        if (pabs) g_u[row] = u;
        float a = fminf(powf(1.0f / (expf(u) * acc), PC), HUGEF);
        g_a[row] = a;
        swm[warp] = a;
    }
    __syncthreads();
    if (tid == 0) {
        float m = swm[0];
#pragma unroll
        for (int k = 1; k < 8; k++) m = fmaxf(m, swm[k]);
        atomicMax(&g_maxa[it], __float_as_uint(m));
    }
}

// ---------------- col pass (sparse): s2 -> b, max flag (bnew folded in) ----------------
__global__ void __launch_bounds__(256) col_kernel(int it) {
    __shared__ float sav[N];          // a_i * dx (new a)
    __shared__ float sap[N];          // prev a (absorb only)
    __shared__ __half vbuf[8][1024];
    __shared__ float swm[8];
    const int b   = blockIdx.x >> 8;  // grid 2048: b(8) x jg(256)
    const int jg  = blockIdx.x & 255;
    const int tid = threadIdx.x;
    const int prev = (it == 0) ? 63 : (it - 1);
    const bool pabs = (__uint_as_float(g_maxa[prev]) > BIGF) ||
                      (__uint_as_float(g_maxb[prev]) > BIGF);
    const int base = b * N;

    for (int i = tid; i < N; i += 256) {
        sav[i] = g_a[base + i] * DXY;
        if (pabs) sap[i] = g_aprev[base + i];
    }
    __syncthreads();

    const int warp = tid >> 5, lane = tid & 31;
    const int j = jg * 8 + warp;
    const int col = base + j;

    uint2 mw = *(const uint2*)&cmask()[(size_t)col * 64 + 2 * lane];
    unsigned c01 = __popc(mw.x) + __popc(mw.y);
    unsigned inc = c01;
#pragma unroll
    for (int d = 1; d < 32; d <<= 1) {
        unsigned n = __shfl_up_sync(0xFFFFFFFFu, inc, d);
        if (lane >= d) inc += n;
    }
    unsigned total = __shfl_sync(0xFFFFFFFFu, inc, 31);
    unsigned excl = inc - c01;
    unsigned vb = (lane == 0) ? g_cbase[col] : 0u;
    vb = __shfl_sync(0xFFFFFFFFu, vb, 0);

    const __half* __restrict__ src = cvals() + vb;
    unsigned tcl = total < 1024u ? total : 1024u;
    for (unsigned t = lane; t < tcl; t += 32) vbuf[warp][t] = src[t];
    __syncwarp();

    float bprev = g_b[col];   // read before overwrite (absorb factor)
    float acc = 0.0f;
    if (!pabs) {
        unsigned o = excl;
        int ib = 64 * lane;
        unsigned m = mw.x;
        while (m) {
            int p = __ffs(m) - 1; m &= m - 1u;
            acc = fmaf(__half2float(vbuf[warp][o++]), sav[ib + p], acc);
        }
        ib += 32; m = mw.y;
        while (m) {
            int p = __ffs(m) - 1; m &= m - 1u;
            acc = fmaf(__half2float(vbuf[warp][o++]), sav[ib + p], acc);
        }
    } else {
        // absorb: rescale CSC values by aprev_i * bprev_j, then sum with new a
        unsigned o = excl;
        int ib = 64 * lane;
#pragma unroll
        for (int w = 0; w < 2; w++) {
            unsigned m = (w == 0) ? mw.x : mw.y;
            int io = ib + w * 32;
            while (m) {
                int p = __ffs(m) - 1; m &= m - 1u;
                float kn = fminf(__half2float(vbuf[warp][o]) * sap[io + p] * bprev, HUGEF);
                vbuf[warp][o] = __float2half_rn(kn);
                acc = fmaf(kn, sav[io + p], acc);
                o++;
            }
        }
        __syncwarp();
        __half* dst = cvals() + vb;
        for (unsigned t = lane; t < tcl; t += 32) dst[t] = vbuf[warp][t];
    }

    acc = warp_sum(acc);
    if (lane == 0) {
        float bn = fminf(powf(1.0f / (expf(g_v[col]) * acc), PC), HUGEF);
        g_b[col] = bn;
        swm[warp] = bn;
    }
    __syncthreads();
    if (tid == 0) {
        float m = swm[0];
#pragma unroll
        for (int k = 1; k < 8; k++) m = fmaxf(m, swm[k]);
        atomicMax(&g_maxb[it], __float_as_uint(m));
    }
}

// ---------------- final: K output + row marginals (full precision C) ----------------
__global__ void __launch_bounds__(256) final_row_kernel(const float* __restrict__ C,
                                                        float* __restrict__ KoutArg,
                                                        int useScratch) {
    __shared__ __align__(16) float sv[N];
    float* __restrict__ Kout = useScratch ? (float*)g_buf : KoutArg;
    const int b   = blockIdx.x >> 8;
    const int rb  = blockIdx.x & 255;
    const int tid = threadIdx.x;
    const int base = b * N;
    for (int j = tid; j < N; j += 256) {
        float vn = g_v[base + j] + EPSF * logf(g_b[base + j]);
        sv[j] = vn * INVE;
    }
    __syncthreads();
    const int wid = tid >> 5, lane = tid & 31;
    const int r = rb * 8 + wid;
    float u = g_u[base + r] + EPSF * logf(g_a[base + r]);
    const float us = u * INVE;
    const size_t off = (size_t)(base + r) * N;
    const float4* __restrict__ cp = (const float4*)(C + off);
    float4* __restrict__ kp = (float4*)(Kout + off);
    float accS = 0.f, accC = 0.f;
#pragma unroll 4
    for (int s = 0; s < 16; s++) {
        int idx = s * 32 + lane;
        float4 c = cp[idx];
        float4 v4 = *(const float4*)&sv[idx * 4];
        float4 k;
        k.x = fminf(__expf(fmaf(c.x, -INVE, us + v4.x)), HUGEF);
        k.y = fminf(__expf(fmaf(c.y, -INVE, us + v4.y)), HUGEF);
        k.z = fminf(__expf(fmaf(c.z, -INVE, us + v4.z)), HUGEF);
        k.w = fminf(__expf(fmaf(c.w, -INVE, us + v4.w)), HUGEF);
        kp[idx] = k;
        accS += (k.x + k.y) + (k.z + k.w);
        accC = fmaf(k.x, c.x, accC);
        accC = fmaf(k.y, c.y, accC);
        accC = fmaf(k.z, c.z, accC);
        accC = fmaf(k.w, c.w, accC);
    }
    accS = warp_sum(accS);
    accC = warp_sum(accC);
    if (lane == 0) {
        g_rowsum[base + r] = accS * DXY;
        g_rowkc[base + r]  = accC;
    }
}

// ---------------- final: column marginal partials (read K back) ----------------
__global__ void __launch_bounds__(256) final_col_kernel(const float* __restrict__ KoutArg,
                                                        int useScratch) {
    const float* __restrict__ Kout = useScratch ? (const float*)g_buf : KoutArg;
    const int bx = blockIdx.x;            // 1024 blocks: b(8) x jt(2) x ic(64)
    const int b  = bx >> 7;
    const int jt = (bx >> 6) & 1;
    const int ic = bx & 63;
    const int tid = threadIdx.x;
    const int base = b * N;
    const int i0 = ic * 32;
    const int j0 = jt * 1024 + tid * 4;
    float a0 = 0.f, a1 = 0.f, a2 = 0.f, a3 = 0.f;
    const size_t rb0 = (size_t)(base + i0) * N + j0;
#pragma unroll 8
    for (int i = 0; i < 32; i++) {
        float4 k = *(const float4*)(Kout + rb0 + (size_t)i * N);
        a0 += k.x; a1 += k.y; a2 += k.z; a3 += k.w;
    }
    *(float4*)&g_part[ic][base + j0] = make_float4(a0, a1, a2, a3);
}

// ---------------- final scalars ----------------
__global__ void __launch_bounds__(256) finalize_kernel(float* __restrict__ out) {
    const int b = blockIdx.x;
    const int tid = threadIdx.x;
    const int base = b * N;
    float c1 = 0.f, c2 = 0.f, tr = 0.f;
    for (int i = tid; i < N; i += 256) {
        float x = g_rowsum[base + i];
        float dv = x / (1.0f + SMALLF);
        c1 += dv * logf(dv + SMALLF) - dv + 1.0f;
        tr += g_rowkc[base + i];
    }
    for (int j = tid; j < N; j += 256) {
        float s = 0.f;
#pragma unroll
        for (int p = 0; p < NPART; p++) s += g_part[p][base + j];
        float x = s * DXY;
        float dv = x / (1.0f + SMALLF);
        c2 += dv * logf(dv + SMALLF) - dv + 1.0f;
    }
    __shared__ float s1[256], s2[256], s3[256];
    s1[tid] = c1; s2[tid] = c2; s3[tid] = tr;
    __syncthreads();
    for (int o = 128; o > 0; o >>= 1) {
        if (tid < o) {
            s1[tid] += s1[tid + o];
            s2[tid] += s2[tid + o];
            s3[tid] += s3[tid + o];
        }
        __syncthreads();
    }
    if (tid == 0) {
        float cons  = 4.0f * (s1[0] * DXY + s2[0] * DXY);
        float trans = 4.0f * s3[0] * DXY * DXY;
        out[b]             = cons + trans;
        out[BATCH + b]     = trans;
        out[2 * BATCH + b] = cons;
    }
}

// ---------------- launch ----------------
extern "C" void kernel_launch(void* const* d_in, const int* in_sizes, int n_in,
                              void* d_out, int out_size) {
    const float* C = (const float*)d_in[0];
    float* out = (float*)d_out;
    const int useScratch = (out_size < (int)(TOTE + 3 * BATCH)) ? 1 : 0;
    float* Kout = out + 3 * BATCH;

    init_kernel<<<64, 256>>>();
    build_csr<<<BN / 8, 256>>>(C);
    build_csc<<<512, 256>>>(C);
    for (int it = 0; it < NITER; it++) {
        row_kernel<<<2048, 256>>>(it);
        col_kernel<<<2048, 256>>>(it);
    }
    final_row_kernel<<<2048, 256>>>(C, Kout, useScratch);
    final_col_kernel<<<1024, 256>>>(Kout, useScratch);
    finalize_kernel<<<BATCH, 256>>>(out);
}

// round 8
// speedup vs baseline: 1.5537x; 1.5537x over previous
#include <cuda_runtime.h>
#include <cuda_fp16.h>
#include <math.h>

#define BATCH 8
#define N 2048
#define BN (BATCH * N)
#define TOTE (BATCH * N * N)          // 33554432 elements
#define NPART 64
#define NITER 50
#define STRIDE 512                    // fixed u32 entries per row/col stream

#define EPSF   0.01f
#define BIGF   1e20f
#define HUGEF  1e30f
#define SMALLF 1e-7f
#define DXY    (1.0f / 2048.0f)

static constexpr float INVE = 1.0f / 0.01f;          // 1/eps
static constexpr float PC   = 1.0f / (1.0f + 0.01f); // p_coef

// ---------------- device state ----------------
// g_buf (128 MB), phase-aliased:
//  Loop phase:   [0,32MB)   CSR packed entries: (j_idx<<16)|fp16(K), BN rows x 512 u32
//                [32,64MB)  CSC packed entries: (i_idx<<16)|fp16(K), BN cols x 512 u32
//  Final phase:  whole buffer = fallback fp32 K target (sparse data dead)
static __device__ float4 g_buf[TOTE / 4];        // 128 MB
static __device__ float g_u[BN];
static __device__ float g_v[BN];
static __device__ float g_a[BN];
static __device__ float g_aprev[BN];
static __device__ float g_b[BN];
static __device__ unsigned g_rn[BN];
static __device__ unsigned g_cn[BN];
static __device__ float g_part[NPART][BN];       // finals only
static __device__ float g_rowsum[BN];
static __device__ float g_rowkc[BN];
static __device__ unsigned g_maxa[64];
static __device__ unsigned g_maxb[64];

__device__ __forceinline__ unsigned* rvals32() { return (unsigned*)g_buf; }
__device__ __forceinline__ unsigned* cvals32() { return (unsigned*)((char*)g_buf + (32u << 20)); }

__device__ __forceinline__ float entry_val(unsigned e) {
    return __half2float(__ushort_as_half((unsigned short)(e & 0xFFFFu)));
}

__device__ __forceinline__ float warp_sum(float x) {
#pragma unroll
    for (int o = 16; o; o >>= 1) x += __shfl_xor_sync(0xFFFFFFFFu, x, o);
    return x;
}

// ---------------- init ----------------
__global__ void init_kernel() {
    int g = blockIdx.x * 256 + threadIdx.x;
    if (g < BN) {
        g_u[g] = 0.0f;
        g_v[g] = 0.0f;
        g_b[g] = 1.0f;
    }
    if (g < 64) { g_maxa[g] = 0u; g_maxb[g] = 0u; }
}

// ---------------- build CSR: packed (idx|val) per row ----------------
__global__ void __launch_bounds__(256) build_csr(const float* __restrict__ C) {
    const int warp = threadIdx.x >> 5, lane = threadIdx.x & 31;
    const int row = blockIdx.x * 8 + warp;        // grid BN/8
    const float* __restrict__ cr = C + (size_t)row * N;
    unsigned* __restrict__ dst = rvals32() + (size_t)row * STRIDE;
    unsigned cnt = 0;
#pragma unroll 4
    for (int g = 0; g < 64; g++) {
        float x = __expf(cr[g * 32 + lane] * -INVE);
        __half h = __float2half_rn(x);
        unsigned hb = (unsigned)__half_as_ushort(h);
        bool nz = hb != 0u;
        unsigned m = __ballot_sync(0xFFFFFFFFu, nz);
        unsigned pre = __popc(m & ((1u << lane) - 1u));
        if (nz) {
            unsigned pos = cnt + pre;
            if (pos < STRIDE) dst[pos] = ((unsigned)(g * 32 + lane) << 16) | hb;
        }
        cnt += __popc(m);
    }
    if (cnt > STRIDE) cnt = STRIDE;
    unsigned pad = (cnt + 127u) & ~127u;
    for (unsigned t = cnt + lane; t < pad; t += 32) dst[t] = 0u;
    if (lane == 0) g_rn[row] = cnt;
}

// ---------------- build CSC: packed (idx|val) per col (tiled transpose) ----------------
__global__ void __launch_bounds__(256) build_csc(const float* __restrict__ C) {
    __shared__ float tile[32][33];
    const int bb = blockIdx.x >> 6;               // grid 512: b(8) x jg(64)
    const int jg = blockIdx.x & 63;
    const int warp = threadIdx.x >> 5, lane = threadIdx.x & 31;
    unsigned cnt[4] = {0u, 0u, 0u, 0u};

    for (int chunk = 0; chunk < 64; chunk++) {
        __syncthreads();
#pragma unroll
        for (int s = 0; s < 4; s++) {
            int il = s * 8 + warp;
            tile[il][lane] = C[((size_t)(bb * N + chunk * 32 + il)) * N + jg * 32 + lane];
        }
        __syncthreads();
#pragma unroll
        for (int q = 0; q < 4; q++) {
            int jc = warp * 4 + q;
            float x = __expf(tile[lane][jc] * -INVE);
            __half h = __float2half_rn(x);
            unsigned hb = (unsigned)__half_as_ushort(h);
            bool nz = hb != 0u;
            unsigned m = __ballot_sync(0xFFFFFFFFu, nz);
            unsigned pre = __popc(m & ((1u << lane) - 1u));
            if (nz) {
                unsigned pos = cnt[q] + pre;
                if (pos < STRIDE)
                    cvals32()[(size_t)(bb * N + jg * 32 + jc) * STRIDE + pos] =
                        ((unsigned)(chunk * 32 + lane) << 16) | hb;
            }
            cnt[q] += __popc(m);
        }
    }
#pragma unroll
    for (int q = 0; q < 4; q++) {
        int jc = warp * 4 + q;
        int col = bb * N + jg * 32 + jc;
        unsigned c = cnt[q] > STRIDE ? STRIDE : cnt[q];
        unsigned pad = (c + 127u) & ~127u;
        unsigned* dst = cvals32() + (size_t)col * STRIDE;
        for (unsigned t = c + lane; t < pad; t += 32) dst[t] = 0u;
        if (lane == 0) g_cn[col] = c;
    }
}

// ---------------- row pass (sparse): s = sum_j K~ b_j dy -> a ----------------
__global__ void __launch_bounds__(256) row_kernel(int it) {
    __shared__ float sbv[N];          // b_j * dy
    __shared__ float swm[8];
    const int b   = blockIdx.x >> 8;
    const int rb  = blockIdx.x & 255;
    const int tid = threadIdx.x;
    const int prev = (it == 0) ? 63 : (it - 1);
    const bool pabs = (__uint_as_float(g_maxa[prev]) > BIGF) ||
                      (__uint_as_float(g_maxb[prev]) > BIGF);
    const int base = b * N;

    for (int j = tid; j < N; j += 256) {
        float bn = g_b[base + j];
        sbv[j] = bn * DXY;
        if (pabs && rb == 0) g_v[base + j] += EPSF * logf(bn);
    }
    __syncthreads();

    const int warp = tid >> 5, lane = tid & 31;
    const int row = base + rb * 8 + warp;
    float u = g_u[row];
    const unsigned cnt = g_rn[row];
    const int nch = (int)((cnt + 127u) >> 7);
    uint4* vp = (uint4*)(rvals32() + (size_t)row * STRIDE);

    float acc = 0.0f;
    if (!pabs) {
        float a0 = 0.f, a1 = 0.f, a2 = 0.f, a3 = 0.f;
        for (int ch = 0; ch < nch; ch++) {
            uint4 p = vp[ch * 32 + lane];
            a0 = fmaf(entry_val(p.x), sbv[p.x >> 16], a0);
            a1 = fmaf(entry_val(p.y), sbv[p.y >> 16], a1);
            a2 = fmaf(entry_val(p.z), sbv[p.z >> 16], a2);
            a3 = fmaf(entry_val(p.w), sbv[p.w >> 16], a3);
        }
        acc = (a0 + a1) + (a2 + a3);
    } else {
        // absorb: K~ <- clip(K~ * aold * b_j); s = sum K~_new * dy
        float aold = g_a[row];
        if (lane == 0) g_aprev[row] = aold;
        u += EPSF * logf(aold);
        for (int ch = 0; ch < nch; ch++) {
            uint4 p = vp[ch * 32 + lane];
            uint4 o;
#pragma unroll
            for (int q = 0; q < 4; q++) {
                unsigned e = (&p.x)[q];
                unsigned idx = e >> 16;
                float braw = sbv[idx] * (float)N;
                float kn = fminf(entry_val(e) * aold * braw, HUGEF);
                acc += kn;
                (&o.x)[q] = (idx << 16) | (unsigned)__half_as_ushort(__float2half_rn(kn));
            }
            vp[ch * 32 + lane] = o;
        }
        acc *= DXY;
    }

    acc = warp_sum(acc);
    if (lane == 0) {
        if (pabs) g_u[row] = u;
        float a = fminf(powf(1.0f / (expf(u) * acc), PC), HUGEF);
        g_a[row] = a;
        swm[warp] = a;
    }
    __syncthreads();
    if (tid == 0) {
        float m = swm[0];
#pragma unroll
        for (int k = 1; k < 8; k++) m = fmaxf(m, swm[k]);
        atomicMax(&g_maxa[it], __float_as_uint(m));
    }
}

// ---------------- col pass (sparse): s2 -> b, max flag (bnew folded in) ----------------
__global__ void __launch_bounds__(256) col_kernel(int it) {
    __shared__ float sav[N];          // a_i * dx (new a)
    __shared__ float sap[N];          // prev a (absorb only)
    __shared__ float swm[8];
    const int b   = blockIdx.x >> 8;  // grid 2048: b(8) x jg(256)
    const int jg  = blockIdx.x & 255;
    const int tid = threadIdx.x;
    const int prev = (it == 0) ? 63 : (it - 1);
    const bool pabs = (__uint_as_float(g_maxa[prev]) > BIGF) ||
                      (__uint_as_float(g_maxb[prev]) > BIGF);
    const int base = b * N;

    for (int i = tid; i < N; i += 256) {
        sav[i] = g_a[base + i] * DXY;
        if (pabs) sap[i] = g_aprev[base + i];
    }
    __syncthreads();

    const int warp = tid >> 5, lane = tid & 31;
    const int col = base + jg * 8 + warp;
    const unsigned cnt = g_cn[col];
    const int nch = (int)((cnt + 127u) >> 7);
    uint4* vp = (uint4*)(cvals32() + (size_t)col * STRIDE);

    float bprev = g_b[col];   // read before overwrite (absorb factor)
    float acc = 0.0f;
    if (!pabs) {
        float a0 = 0.f, a1 = 0.f, a2 = 0.f, a3 = 0.f;
        for (int ch = 0; ch < nch; ch++) {
            uint4 p = vp[ch * 32 + lane];
            a0 = fmaf(entry_val(p.x), sav[p.x >> 16], a0);
            a1 = fmaf(entry_val(p.y), sav[p.y >> 16], a1);
            a2 = fmaf(entry_val(p.z), sav[p.z >> 16], a2);
            a3 = fmaf(entry_val(p.w), sav[p.w >> 16], a3);
        }
        acc = (a0 + a1) + (a2 + a3);
    } else {
        // absorb: K~csc <- clip(K~ * aprev_i * bprev_j), then sum with new a
        for (int ch = 0; ch < nch; ch++) {
            uint4 p = vp[ch * 32 + lane];
            uint4 o;
#pragma unroll
            for (int q = 0; q < 4; q++) {
                unsigned e = (&p.x)[q];
                unsigned idx = e >> 16;
                float kn = fminf(entry_val(e) * sap[idx] * bprev, HUGEF);
                acc = fmaf(kn, sav[idx], acc);
                (&o.x)[q] = (idx << 16) | (unsigned)__half_as_ushort(__float2half_rn(kn));
            }
            vp[ch * 32 + lane] = o;
        }
    }

    acc = warp_sum(acc);
    if (lane == 0) {
        float bn = fminf(powf(1.0f / (expf(g_v[col]) * acc), PC), HUGEF);
        g_b[col] = bn;
        swm[warp] = bn;
    }
    __syncthreads();
    if (tid == 0) {
        float m = swm[0];
#pragma unroll
        for (int k = 1; k < 8; k++) m = fmaxf(m, swm[k]);
        atomicMax(&g_maxb[it], __float_as_uint(m));
    }
}

// ---------------- final: K output + row marginals (full precision C) ----------------
__global__ void __launch_bounds__(256) final_row_kernel(const float* __restrict__ C,
                                                        float* __restrict__ KoutArg,
                                                        int useScratch) {
    __shared__ __align__(16) float sv[N];
    float* __restrict__ Kout = useScratch ? (float*)g_buf : KoutArg;
    const int b   = blockIdx.x >> 8;
    const int rb  = blockIdx.x & 255;
    const int tid = threadIdx.x;
    const int base = b * N;
    for (int j = tid; j < N; j += 256) {
        float vn = g_v[base + j] + EPSF * logf(g_b[base + j]);
        sv[j] = vn * INVE;
    }
    __syncthreads();
    const int wid = tid >> 5, lane = tid & 31;
    const int r = rb * 8 + wid;
    float u = g_u[base + r] + EPSF * logf(g_a[base + r]);
    const float us = u * INVE;
    const size_t off = (size_t)(base + r) * N;
    const float4* __restrict__ cp = (const float4*)(C + off);
    float4* __restrict__ kp = (float4*)(Kout + off);
    float accS = 0.f, accC = 0.f;
#pragma unroll 4
    for (int s = 0; s < 16; s++) {
        int idx = s * 32 + lane;
        float4 c = cp[idx];
        float4 v4 = *(const float4*)&sv[idx * 4];
        float4 k;
        k.x = fminf(__expf(fmaf(c.x, -INVE, us + v4.x)), HUGEF);
        k.y = fminf(__expf(fmaf(c.y, -INVE, us + v4.y)), HUGEF);
        k.z = fminf(__expf(fmaf(c.z, -INVE, us + v4.z)), HUGEF);
        k.w = fminf(__expf(fmaf(c.w, -INVE, us + v4.w)), HUGEF);
        kp[idx] = k;
        accS += (k.x + k.y) + (k.z + k.w);
        accC = fmaf(k.x, c.x, accC);
        accC = fmaf(k.y, c.y, accC);
        accC = fmaf(k.z, c.z, accC);
        accC = fmaf(k.w, c.w, accC);
    }
    accS = warp_sum(accS);
    accC = warp_sum(accC);
    if (lane == 0) {
        g_rowsum[base + r] = accS * DXY;
        g_rowkc[base + r]  = accC;
    }
}

// ---------------- final: column marginal partials (read K back) ----------------
__global__ void __launch_bounds__(256) final_col_kernel(const float* __restrict__ KoutArg,
                                                        int useScratch) {
    const float* __restrict__ Kout = useScratch ? (const float*)g_buf : KoutArg;
    const int bx = blockIdx.x;            // 1024 blocks: b(8) x jt(2) x ic(64)
    const int b  = bx >> 7;
    const int jt = (bx >> 6) & 1;
    const int ic = bx & 63;
    const int tid = threadIdx.x;
    const int base = b * N;
    const int i0 = ic * 32;
    const int j0 = jt * 1024 + tid * 4;
    float a0 = 0.f, a1 = 0.f, a2 = 0.f, a3 = 0.f;
    const size_t rb0 = (size_t)(base + i0) * N + j0;
#pragma unroll 8
    for (int i = 0; i < 32; i++) {
        float4 k = *(const float4*)(Kout + rb0 + (size_t)i * N);
        a0 += k.x; a1 += k.y; a2 += k.z; a3 += k.w;
    }
    *(float4*)&g_part[ic][base + j0] = make_float4(a0, a1, a2, a3);
}

// ---------------- final scalars ----------------
__global__ void __launch_bounds__(256) finalize_kernel(float* __restrict__ out) {
    const int b = blockIdx.x;
    const int tid = threadIdx.x;
    const int base = b * N;
    float c1 = 0.f, c2 = 0.f, tr = 0.f;
    for (int i = tid; i < N; i += 256) {
        float x = g_rowsum[base + i];
        float dv = x / (1.0f + SMALLF);
        c1 += dv * logf(dv + SMALLF) - dv + 1.0f;
        tr += g_rowkc[base + i];
    }
    for (int j = tid; j < N; j += 256) {
        float s = 0.f;
#pragma unroll
        for (int p = 0; p < NPART; p++) s += g_part[p][base + j];
        float x = s * DXY;
        float dv = x / (1.0f + SMALLF);
        c2 += dv * logf(dv + SMALLF) - dv + 1.0f;
    }
    __shared__ float s1[256], s2[256], s3[256];
    s1[tid] = c1; s2[tid] = c2; s3[tid] = tr;
    __syncthreads();
    for (int o = 128; o > 0; o >>= 1) {
        if (tid < o) {
            s1[tid] += s1[tid + o];
            s2[tid] += s2[tid + o];
            s3[tid] += s3[tid + o];
        }
        __syncthreads();
    }
    if (tid == 0) {
        float cons  = 4.0f * (s1[0] * DXY + s2[0] * DXY);
        float trans = 4.0f * s3[0] * DXY * DXY;
        out[b]             = cons + trans;
        out[BATCH + b]     = trans;
        out[2 * BATCH + b] = cons;
    }
}

// ---------------- launch ----------------
extern "C" void kernel_launch(void* const* d_in, const int* in_sizes, int n_in,
                              void* d_out, int out_size) {
    const float* C = (const float*)d_in[0];
    float* out = (float*)d_out;
    const int useScratch = (out_size < (int)(TOTE + 3 * BATCH)) ? 1 : 0;
    float* Kout = out + 3 * BATCH;

    init_kernel<<<64, 256>>>();
    build_csr<<<BN / 8, 256>>>(C);
    build_csc<<<512, 256>>>(C);
    for (int it = 0; it < NITER; it++) {
        row_kernel<<<2048, 256>>>(it);
        col_kernel<<<2048, 256>>>(it);
    }
    final_row_kernel<<<2048, 256>>>(C, Kout, useScratch);
    final_col_kernel<<<1024, 256>>>(Kout, useScratch);
    finalize_kernel<<<BATCH, 256>>>(out);
}

// round 9
// speedup vs baseline: 1.5673x; 1.0087x over previous
#include <cuda_runtime.h>
#include <cuda_fp16.h>
#include <math.h>

#define BATCH 8
#define N 2048
#define BN (BATCH * N)
#define TOTE (BATCH * N * N)          // 33554432 elements
#define NPART 64
#define NITER 50
#define STRIDE 512                    // fixed u32 entries per row/col stream (fully padded)

#define EPSF   0.01f
#define BIGF   1e20f
#define HUGEF  1e30f
#define SMALLF 1e-7f
#define DXY    (1.0f / 2048.0f)

static constexpr float INVE = 1.0f / 0.01f;          // 1/eps
static constexpr float PC   = 1.0f / (1.0f + 0.01f); // p_coef

// ---------------- device state ----------------
// g_buf (128 MB), phase-aliased:
//  Loop phase:   [0,32MB)   CSR packed entries: (j_idx<<16)|fp16(K), BN rows x 512 u32, zero-padded
//                [32,64MB)  CSC packed entries: (i_idx<<16)|fp16(K), BN cols x 512 u32, zero-padded
//  Final phase:  whole buffer = fallback fp32 K target (sparse data dead)
static __device__ float4 g_buf[TOTE / 4];        // 128 MB
static __device__ float g_u[BN];
static __device__ float g_v[BN];
static __device__ float g_a[BN];
static __device__ float g_aprev[BN];
static __device__ float g_b[BN];
static __device__ float g_part[NPART][BN];       // finals only
static __device__ float g_rowsum[BN];
static __device__ float g_rowkc[BN];
static __device__ unsigned g_maxa[64];
static __device__ unsigned g_maxb[64];

__device__ __forceinline__ unsigned* rvals32() { return (unsigned*)g_buf; }
__device__ __forceinline__ unsigned* cvals32() { return (unsigned*)((char*)g_buf + (32u << 20)); }

__device__ __forceinline__ float entry_val(unsigned e) {
    return __half2float(__ushort_as_half((unsigned short)(e & 0xFFFFu)));
}

__device__ __forceinline__ float warp_sum(float x) {
#pragma unroll
    for (int o = 16; o; o >>= 1) x += __shfl_xor_sync(0xFFFFFFFFu, x, o);
    return x;
}

// ---------------- init ----------------
__global__ void init_kernel() {
    int g = blockIdx.x * 256 + threadIdx.x;
    if (g < BN) {
        g_u[g] = 0.0f;
        g_v[g] = 0.0f;
        g_b[g] = 1.0f;
    }
    if (g < 64) { g_maxa[g] = 0u; g_maxb[g] = 0u; }
}

// ---------------- build CSR: packed (idx|val) per row, zero-padded to STRIDE ----------------
__global__ void __launch_bounds__(256) build_csr(const float* __restrict__ C) {
    const int warp = threadIdx.x >> 5, lane = threadIdx.x & 31;
    const int row = blockIdx.x * 8 + warp;        // grid BN/8
    const float* __restrict__ cr = C + (size_t)row * N;
    unsigned* __restrict__ dst = rvals32() + (size_t)row * STRIDE;
    unsigned cnt = 0;
#pragma unroll 4
    for (int g = 0; g < 64; g++) {
        float x = __expf(cr[g * 32 + lane] * -INVE);
        __half h = __float2half_rn(x);
        unsigned hb = (unsigned)__half_as_ushort(h);
        bool nz = hb != 0u;
        unsigned m = __ballot_sync(0xFFFFFFFFu, nz);
        unsigned pre = __popc(m & ((1u << lane) - 1u));
        if (nz) {
            unsigned pos = cnt + pre;
            if (pos < STRIDE) dst[pos] = ((unsigned)(g * 32 + lane) << 16) | hb;
        }
        cnt += __popc(m);
    }
    if (cnt > STRIDE) cnt = STRIDE;
    for (unsigned t = cnt + lane; t < STRIDE; t += 32) dst[t] = 0u;
}

// ---------------- build CSC: packed (idx|val) per col, zero-padded to STRIDE ----------------
__global__ void __launch_bounds__(256) build_csc(const float* __restrict__ C) {
    __shared__ float tile[32][33];
    const int bb = blockIdx.x >> 6;               // grid 512: b(8) x jg(64)
    const int jg = blockIdx.x & 63;
    const int warp = threadIdx.x >> 5, lane = threadIdx.x & 31;
    unsigned cnt[4] = {0u, 0u, 0u, 0u};

    for (int chunk = 0; chunk < 64; chunk++) {
        __syncthreads();
#pragma unroll
        for (int s = 0; s < 4; s++) {
            int il = s * 8 + warp;
            tile[il][lane] = C[((size_t)(bb * N + chunk * 32 + il)) * N + jg * 32 + lane];
        }
        __syncthreads();
#pragma unroll
        for (int q = 0; q < 4; q++) {
            int jc = warp * 4 + q;
            float x = __expf(tile[lane][jc] * -INVE);
            __half h = __float2half_rn(x);
            unsigned hb = (unsigned)__half_as_ushort(h);
            bool nz = hb != 0u;
            unsigned m = __ballot_sync(0xFFFFFFFFu, nz);
            unsigned pre = __popc(m & ((1u << lane) - 1u));
            if (nz) {
                unsigned pos = cnt[q] + pre;
                if (pos < STRIDE)
                    cvals32()[(size_t)(bb * N + jg * 32 + jc) * STRIDE + pos] =
                        ((unsigned)(chunk * 32 + lane) << 16) | hb;
            }
            cnt[q] += __popc(m);
        }
    }
#pragma unroll
    for (int q = 0; q < 4; q++) {
        int jc = warp * 4 + q;
        int col = bb * N + jg * 32 + jc;
        unsigned c = cnt[q] > STRIDE ? STRIDE : cnt[q];
        unsigned* dst = cvals32() + (size_t)col * STRIDE;
        for (unsigned t = c + lane; t < STRIDE; t += 32) dst[t] = 0u;
    }
}

// ---------------- row pass (sparse): s = sum_j K~ b_j dy -> a ----------------
__global__ void __launch_bounds__(256) row_kernel(int it) {
    __shared__ float sbv[N];          // b_j * dy
    __shared__ float swm[8];
    const int b   = blockIdx.x >> 8;
    const int rb  = blockIdx.x & 255;
    const int tid = threadIdx.x;
    const int prev = (it == 0) ? 63 : (it - 1);
    const bool pabs = (__uint_as_float(g_maxa[prev]) > BIGF) ||
                      (__uint_as_float(g_maxb[prev]) > BIGF);
    const int base = b * N;

    for (int j = tid; j < N; j += 256) {
        float bn = g_b[base + j];
        sbv[j] = bn * DXY;
        if (pabs && rb == 0) g_v[base + j] += EPSF * logf(bn);
    }
    __syncthreads();

    const int warp = tid >> 5, lane = tid & 31;
    const int row = base + rb * 8 + warp;
    float u = g_u[row];
    uint4* vp = (uint4*)(rvals32() + (size_t)row * STRIDE);

    float acc = 0.0f;
    if (!pabs) {
        // fixed 4 chunks, all loads issued up-front (MLP=4)
        uint4 p0 = vp[lane];
        uint4 p1 = vp[32 + lane];
        uint4 p2 = vp[64 + lane];
        uint4 p3 = vp[96 + lane];
        float a0 = 0.f, a1 = 0.f, a2 = 0.f, a3 = 0.f;
        a0 = fmaf(entry_val(p0.x), sbv[p0.x >> 16], a0);
        a1 = fmaf(entry_val(p0.y), sbv[p0.y >> 16], a1);
        a2 = fmaf(entry_val(p0.z), sbv[p0.z >> 16], a2);
        a3 = fmaf(entry_val(p0.w), sbv[p0.w >> 16], a3);
        a0 = fmaf(entry_val(p1.x), sbv[p1.x >> 16], a0);
        a1 = fmaf(entry_val(p1.y), sbv[p1.y >> 16], a1);
        a2 = fmaf(entry_val(p1.z), sbv[p1.z >> 16], a2);
        a3 = fmaf(entry_val(p1.w), sbv[p1.w >> 16], a3);
        a0 = fmaf(entry_val(p2.x), sbv[p2.x >> 16], a0);
        a1 = fmaf(entry_val(p2.y), sbv[p2.y >> 16], a1);
        a2 = fmaf(entry_val(p2.z), sbv[p2.z >> 16], a2);
        a3 = fmaf(entry_val(p2.w), sbv[p2.w >> 16], a3);
        a0 = fmaf(entry_val(p3.x), sbv[p3.x >> 16], a0);
        a1 = fmaf(entry_val(p3.y), sbv[p3.y >> 16], a1);
        a2 = fmaf(entry_val(p3.z), sbv[p3.z >> 16], a2);
        a3 = fmaf(entry_val(p3.w), sbv[p3.w >> 16], a3);
        acc = (a0 + a1) + (a2 + a3);
    } else {
        // absorb: K~ <- clip(K~ * aold * b_j); s = sum K~_new * dy
        float aold = g_a[row];
        if (lane == 0) g_aprev[row] = aold;
        u += EPSF * logf(aold);
#pragma unroll
        for (int ch = 0; ch < 4; ch++) {
            uint4 p = vp[ch * 32 + lane];
            uint4 o;
#pragma unroll
            for (int q = 0; q < 4; q++) {
                unsigned e = (&p.x)[q];
                unsigned idx = e >> 16;
                float braw = sbv[idx] * (float)N;
                float kn = fminf(entry_val(e) * aold * braw, HUGEF);
                acc += kn;
                (&o.x)[q] = (idx << 16) | (unsigned)__half_as_ushort(__float2half_rn(kn));
            }
            vp[ch * 32 + lane] = o;
        }
        acc *= DXY;
    }

    acc = warp_sum(acc);
    if (lane == 0) {
        if (pabs) g_u[row] = u;
        float a = fminf(powf(1.0f / (expf(u) * acc), PC), HUGEF);
        g_a[row] = a;
        swm[warp] = a;
    }
    __syncthreads();
    if (tid == 0) {
        float m = swm[0];
#pragma unroll
        for (int k = 1; k < 8; k++) m = fmaxf(m, swm[k]);
        atomicMax(&g_maxa[it], __float_as_uint(m));
    }
}

// ---------------- col pass (sparse): s2 -> b, max flag (bnew folded in) ----------------
__global__ void __launch_bounds__(256) col_kernel(int it) {
    __shared__ float sav[N];          // a_i * dx (new a)
    __shared__ float sap[N];          // prev a (absorb only)
    __shared__ float swm[8];
    const int b   = blockIdx.x >> 8;  // grid 2048: b(8) x jg(256)
    const int jg  = blockIdx.x & 255;
    const int tid = threadIdx.x;
    const int prev = (it == 0) ? 63 : (it - 1);
    const bool pabs = (__uint_as_float(g_maxa[prev]) > BIGF) ||
                      (__uint_as_float(g_maxb[prev]) > BIGF);
    const int base = b * N;

    for (int i = tid; i < N; i += 256) {
        sav[i] = g_a[base + i] * DXY;
        if (pabs) sap[i] = g_aprev[base + i];
    }
    __syncthreads();

    const int warp = tid >> 5, lane = tid & 31;
    const int col = base + jg * 8 + warp;
    uint4* vp = (uint4*)(cvals32() + (size_t)col * STRIDE);

    float bprev = g_b[col];   // read before overwrite (absorb factor)
    float acc = 0.0f;
    if (!pabs) {
        uint4 p0 = vp[lane];
        uint4 p1 = vp[32 + lane];
        uint4 p2 = vp[64 + lane];
        uint4 p3 = vp[96 + lane];
        float a0 = 0.f, a1 = 0.f, a2 = 0.f, a3 = 0.f;
        a0 = fmaf(entry_val(p0.x), sav[p0.x >> 16], a0);
        a1 = fmaf(entry_val(p0.y), sav[p0.y >> 16], a1);
        a2 = fmaf(entry_val(p0.z), sav[p0.z >> 16], a2);
        a3 = fmaf(entry_val(p0.w), sav[p0.w >> 16], a3);
        a0 = fmaf(entry_val(p1.x), sav[p1.x >> 16], a0);
        a1 = fmaf(entry_val(p1.y), sav[p1.y >> 16], a1);
        a2 = fmaf(entry_val(p1.z), sav[p1.z >> 16], a2);
        a3 = fmaf(entry_val(p1.w), sav[p1.w >> 16], a3);
        a0 = fmaf(entry_val(p2.x), sav[p2.x >> 16], a0);
        a1 = fmaf(entry_val(p2.y), sav[p2.y >> 16], a1);
        a2 = fmaf(entry_val(p2.z), sav[p2.z >> 16], a2);
        a3 = fmaf(entry_val(p2.w), sav[p2.w >> 16], a3);
        a0 = fmaf(entry_val(p3.x), sav[p3.x >> 16], a0);
        a1 = fmaf(entry_val(p3.y), sav[p3.y >> 16], a1);
        a2 = fmaf(entry_val(p3.z), sav[p3.z >> 16], a2);
        a3 = fmaf(entry_val(p3.w), sav[p3.w >> 16], a3);
        acc = (a0 + a1) + (a2 + a3);
    } else {
        // absorb: K~csc <- clip(K~ * aprev_i * bprev_j), then sum with new a
#pragma unroll
        for (int ch = 0; ch < 4; ch++) {
            uint4 p = vp[ch * 32 + lane];
            uint4 o;
#pragma unroll
            for (int q = 0; q < 4; q++) {
                unsigned e = (&p.x)[q];
                unsigned idx = e >> 16;
                float kn = fminf(entry_val(e) * sap[idx] * bprev, HUGEF);
                acc = fmaf(kn, sav[idx], acc);
                (&o.x)[q] = (idx << 16) | (unsigned)__half_as_ushort(__float2half_rn(kn));
            }
            vp[ch * 32 + lane] = o;
        }
    }

    acc = warp_sum(acc);
    if (lane == 0) {
        float bn = fminf(powf(1.0f / (expf(g_v[col]) * acc), PC), HUGEF);
        g_b[col] = bn;
        swm[warp] = bn;
    }
    __syncthreads();
    if (tid == 0) {
        float m = swm[0];
#pragma unroll
        for (int k = 1; k < 8; k++) m = fmaxf(m, swm[k]);
        atomicMax(&g_maxb[it], __float_as_uint(m));
    }
}

// ---------------- final: K output + row marginals (full precision C) ----------------
__global__ void __launch_bounds__(256) final_row_kernel(const float* __restrict__ C,
                                                        float* __restrict__ KoutArg,
                                                        int useScratch) {
    __shared__ __align__(16) float sv[N];
    float* __restrict__ Kout = useScratch ? (float*)g_buf : KoutArg;
    const int b   = blockIdx.x >> 8;
    const int rb  = blockIdx.x & 255;
    const int tid = threadIdx.x;
    const int base = b * N;
    for (int j = tid; j < N; j += 256) {
        float vn = g_v[base + j] + EPSF * logf(g_b[base + j]);
        sv[j] = vn * INVE;
    }
    __syncthreads();
    const int wid = tid >> 5, lane = tid & 31;
    const int r = rb * 8 + wid;
    float u = g_u[base + r] + EPSF * logf(g_a[base + r]);
    const float us = u * INVE;
    const size_t off = (size_t)(base + r) * N;
    const float4* __restrict__ cp = (const float4*)(C + off);
    float4* __restrict__ kp = (float4*)(Kout + off);
    float accS = 0.f, accC = 0.f;
#pragma unroll 4
    for (int s = 0; s < 16; s++) {
        int idx = s * 32 + lane;
        float4 c = cp[idx];
        float4 v4 = *(const float4*)&sv[idx * 4];
        float4 k;
        k.x = fminf(__expf(fmaf(c.x, -INVE, us + v4.x)), HUGEF);
        k.y = fminf(__expf(fmaf(c.y, -INVE, us + v4.y)), HUGEF);
        k.z = fminf(__expf(fmaf(c.z, -INVE, us + v4.z)), HUGEF);
        k.w = fminf(__expf(fmaf(c.w, -INVE, us + v4.w)), HUGEF);
        kp[idx] = k;
        accS += (k.x + k.y) + (k.z + k.w);
        accC = fmaf(k.x, c.x, accC);
        accC = fmaf(k.y, c.y, accC);
        accC = fmaf(k.z, c.z, accC);
        accC = fmaf(k.w, c.w, accC);
    }
    accS = warp_sum(accS);
    accC = warp_sum(accC);
    if (lane == 0) {
        g_rowsum[base + r] = accS * DXY;
        g_rowkc[base + r]  = accC;
    }
}

// ---------------- final: column marginal partials (read K back) ----------------
__global__ void __launch_bounds__(256) final_col_kernel(const float* __restrict__ KoutArg,
                                                        int useScratch) {
    const float* __restrict__ Kout = useScratch ? (const float*)g_buf : KoutArg;
    const int bx = blockIdx.x;            // 1024 blocks: b(8) x jt(2) x ic(64)
    const int b  = bx >> 7;
    const int jt = (bx >> 6) & 1;
    const int ic = bx & 63;
    const int tid = threadIdx.x;
    const int base = b * N;
    const int i0 = ic * 32;
    const int j0 = jt * 1024 + tid * 4;
    float a0 = 0.f, a1 = 0.f, a2 = 0.f, a3 = 0.f;
    const size_t rb0 = (size_t)(base + i0) * N + j0;
#pragma unroll 8
    for (int i = 0; i < 32; i++) {
        float4 k = *(const float4*)(Kout + rb0 + (size_t)i * N);
        a0 += k.x; a1 += k.y; a2 += k.z; a3 += k.w;
    }
    *(float4*)&g_part[ic][base + j0] = make_float4(a0, a1, a2, a3);
}

// ---------------- final scalars ----------------
__global__ void __launch_bounds__(256) finalize_kernel(float* __restrict__ out) {
    const int b = blockIdx.x;
    const int tid = threadIdx.x;
    const int base = b * N;
    float c1 = 0.f, c2 = 0.f, tr = 0.f;
    for (int i = tid; i < N; i += 256) {
        float x = g_rowsum[base + i];
        float dv = x / (1.0f + SMALLF);
        c1 += dv * logf(dv + SMALLF) - dv + 1.0f;
        tr += g_rowkc[base + i];
    }
    for (int j = tid; j < N; j += 256) {
        float s = 0.f;
#pragma unroll
        for (int p = 0; p < NPART; p++) s += g_part[p][base + j];
        float x = s * DXY;
        float dv = x / (1.0f + SMALLF);
        c2 += dv * logf(dv + SMALLF) - dv + 1.0f;
    }
    __shared__ float s1[256], s2[256], s3[256];
    s1[tid] = c1; s2[tid] = c2; s3[tid] = tr;
    __syncthreads();
    for (int o = 128; o > 0; o >>= 1) {
        if (tid < o) {
            s1[tid] += s1[tid + o];
            s2[tid] += s2[tid + o];
            s3[tid] += s3[tid + o];
        }
        __syncthreads();
    }
    if (tid == 0) {
        float cons  = 4.0f * (s1[0] * DXY + s2[0] * DXY);
        float trans = 4.0f * s3[0] * DXY * DXY;
        out[b]             = cons + trans;
        out[BATCH + b]     = trans;
        out[2 * BATCH + b] = cons;
    }
}

// ---------------- launch ----------------
extern "C" void kernel_launch(void* const* d_in, const int* in_sizes, int n_in,
                              void* d_out, int out_size) {
    const float* C = (const float*)d_in[0];
    float* out = (float*)d_out;
    const int useScratch = (out_size < (int)(TOTE + 3 * BATCH)) ? 1 : 0;
    float* Kout = out + 3 * BATCH;

    init_kernel<<<64, 256>>>();
    build_csr<<<BN / 8, 256>>>(C);
    build_csc<<<512, 256>>>(C);
    for (int it = 0; it < NITER; it++) {
        row_kernel<<<2048, 256>>>(it);
        col_kernel<<<2048, 256>>>(it);
    }
    final_row_kernel<<<2048, 256>>>(C, Kout, useScratch);
    final_col_kernel<<<1024, 256>>>(Kout, useScratch);
    finalize_kernel<<<BATCH, 256>>>(out);
}